// round 1
// baseline (speedup 1.0000x reference)
#include <cuda_runtime.h>

// Compressor_86174223827251 — fused fp32 implementation, f32x2 packed FMA.
//
// Geometry:
//   k[2,16,8192,128], pe[32,128], w_down[5,128,256], w_stop[128,128]
//   nb = 511 windows per (b,h), stride 16, window 32. Output [2,16,512,128].
//   Output slot 0 per (b,h) is Phi(zeros) == 0 exactly (silu(0)=0).
//
// One CTA = 8 windows, fully fused in SMEM:
//   actA [8][32][128] f32  (128 KB)
//   actB [8][16][128] f32  ( 64 KB)
//   wt   [32][256]    f32  ( 32 KB)  -> 229376 B dynamic smem
// Stages ping-pong actA<->actB; weight tiles streamed from L2.

#define NW 8          // windows per CTA
#define NTH 256
#define SMEM_BYTES 229376
#define USE_F32X2 1

__device__ __forceinline__ void ffma2(unsigned long long &d,
                                      unsigned long long a,
                                      unsigned long long b) {
#if USE_F32X2
    asm("fma.rn.f32x2 %0, %1, %2, %0;" : "+l"(d) : "l"(a), "l"(b));
#else
    float2* dp = reinterpret_cast<float2*>(&d);
    const float2* ap = reinterpret_cast<const float2*>(&a);
    const float2* bp = reinterpret_cast<const float2*>(&b);
    dp->x = fmaf(ap->x, bp->x, dp->x);
    dp->y = fmaf(ap->y, bp->y, dp->y);
#endif
}

__device__ __forceinline__ float acc_sum(unsigned long long a) {
    float2 f = *reinterpret_cast<float2*>(&a);
    return f.x + f.y;
}

__device__ __forceinline__ float silu_f(float v) {
    return v / (1.0f + __expf(-v));
}

// One output-column tile (32 cols at base c0) of one merge stage.
// inB:  [NW][2*Rout][128] (compact), outB: [NW][Rout][128] (compact)
// wt:   [32][256] weight tile (rows = output cols c0..c0+31)
// Stage input row r of 256 = concat(inB[2r], inB[2r+1]).
// Tile grid is exactly 256 tiles -> tile index == threadIdx.x.
template<int TR, int TC>
__device__ __forceinline__ void stage_gemm(const float* __restrict__ inB,
                                           float* __restrict__ outB,
                                           const float* __restrict__ wt,
                                           int Rout, int c0) {
    constexpr int tilesC = 32 / TC;
    const int t  = threadIdx.x;
    const int tc = t % tilesC;
    const int tr = t / tilesC;
    const int r0 = tr * TR;            // global row in [0, NW*Rout)
    const int wi = r0 / Rout;          // TR divides Rout -> tile stays in one window
    const int lr0 = r0 - wi * Rout;
    const float* inW = inB + wi * (2 * Rout * 128);

    unsigned long long acc[TR][TC];
#pragma unroll
    for (int ro = 0; ro < TR; ro++)
#pragma unroll
        for (int co = 0; co < TC; co++) acc[ro][co] = 0ull;

#pragma unroll
    for (int h = 0; h < 2; h++) {
        const float* xr[TR];
#pragma unroll
        for (int ro = 0; ro < TR; ro++)
            xr[ro] = inW + (2 * (lr0 + ro) + h) * 128;
        const float* wr[TC];
#pragma unroll
        for (int co = 0; co < TC; co++)
            wr[co] = wt + (tc * TC + co) * 256 + h * 128;

#pragma unroll 8
        for (int k = 0; k < 128; k += 4) {
            ulonglong2 xv[TR], wv[TC];
#pragma unroll
            for (int ro = 0; ro < TR; ro++)
                xv[ro] = *reinterpret_cast<const ulonglong2*>(xr[ro] + k);
#pragma unroll
            for (int co = 0; co < TC; co++)
                wv[co] = *reinterpret_cast<const ulonglong2*>(wr[co] + k);
#pragma unroll
            for (int ro = 0; ro < TR; ro++)
#pragma unroll
                for (int co = 0; co < TC; co++) {
                    ffma2(acc[ro][co], xv[ro].x, wv[co].x);
                    ffma2(acc[ro][co], xv[ro].y, wv[co].y);
                }
        }
    }

#pragma unroll
    for (int ro = 0; ro < TR; ro++)
#pragma unroll
        for (int co = 0; co < TC; co++) {
            float v = acc_sum(acc[ro][co]);
            outB[wi * (Rout * 128) + (lr0 + ro) * 128 + c0 + tc * TC + co] =
                silu_f(v);
        }
}

__global__ void __launch_bounds__(NTH, 1)
compressor_kernel(const float* __restrict__ kin,
                  const float* __restrict__ pe,
                  const float* __restrict__ wdown,
                  const float* __restrict__ wstop,
                  float* __restrict__ out) {
    extern __shared__ float smem[];
    float* actA = smem;                 // [8][32][128] = 32768 floats
    float* actB = smem + 32768;         // [8][16][128] = 16384 floats
    float* wt   = smem + 49152;         // [32][256]    =  8192 floats

    const int tid = threadIdx.x;
    const int gbase = blockIdx.x * NW;  // first window id of this CTA

    // ---- gather: actA[wi][row][d] = k[bh, 16*j + row, d] + pe[row][d] ----
    for (int i = tid; i < NW * 32 * 128 / 4; i += NTH) {
        int wi  = i >> 10;              // 1024 float4 per window
        int rem = i & 1023;
        int row = rem >> 5;             // 32 float4 per row
        int dq  = rem & 31;
        int g   = gbase + wi;
        int bh  = g / 511;
        int j   = g - bh * 511;
        const float4 kv = *reinterpret_cast<const float4*>(
            kin + ((size_t)bh * 8192 + 16 * j + row) * 128 + dq * 4);
        const float4 pv = *reinterpret_cast<const float4*>(pe + row * 128 + dq * 4);
        float4 o;
        o.x = kv.x + pv.x; o.y = kv.y + pv.y;
        o.z = kv.z + pv.z; o.w = kv.w + pv.w;
        *reinterpret_cast<float4*>(actA + wi * 4096 + row * 128 + dq * 4) = o;
    }

    // ---- 5 merge stages ----
    for (int s = 0; s < 5; s++) {
        const float* inB = (s & 1) ? actB : actA;
        float* outB      = (s & 1) ? actA : actB;
        const float* wsrc = wdown + s * 128 * 256;
        const int Rout = 16 >> s;
        for (int ct = 0; ct < 4; ct++) {
            __syncthreads();   // previous compute done before wt overwrite
            {
                const float4* src =
                    reinterpret_cast<const float4*>(wsrc + ct * 32 * 256);
                float4* dst = reinterpret_cast<float4*>(wt);
#pragma unroll
                for (int i = tid; i < 2048; i += NTH) dst[i] = src[i];
            }
            __syncthreads();
            switch (s) {
                case 0:  stage_gemm<4, 4>(inB, outB, wt, Rout, ct * 32); break;
                case 1:  stage_gemm<4, 2>(inB, outB, wt, Rout, ct * 32); break;
                case 2:  stage_gemm<4, 1>(inB, outB, wt, Rout, ct * 32); break;
                case 3:  stage_gemm<2, 1>(inB, outB, wt, Rout, ct * 32); break;
                default: stage_gemm<1, 1>(inB, outB, wt, Rout, ct * 32); break;
            }
        }
    }

    // ---- stop projection: actB[wi][0][0..127] @ w_stop^T, no silu ----
    for (int ct = 0; ct < 2; ct++) {
        __syncthreads();
        {
            const float4* src =
                reinterpret_cast<const float4*>(wstop + ct * 64 * 128);
            float4* dst = reinterpret_cast<float4*>(wt);  // reused as [64][128]
#pragma unroll
            for (int i = tid; i < 2048; i += NTH) dst[i] = src[i];
        }
        __syncthreads();
#pragma unroll
        for (int e2 = 0; e2 < 2; e2++) {
            int e = tid + e2 * NTH;    // 512 outputs: 8 windows x 64 cols
            int r = e >> 6;
            int c = e & 63;
            const float* x  = actB + r * 128;
            const float* wr = wt + c * 128;
            unsigned long long acc = 0ull;
#pragma unroll
            for (int k = 0; k < 128; k += 4) {
                ulonglong2 xv = *reinterpret_cast<const ulonglong2*>(x + k);
                ulonglong2 wv = *reinterpret_cast<const ulonglong2*>(wr + k);
                ffma2(acc, xv.x, wv.x);
                ffma2(acc, xv.y, wv.y);
            }
            float v = acc_sum(acc);
            int g  = gbase + r;
            int bh = g / 511;
            int j  = g - bh * 511;
            out[bh * 65536 + (1 + j) * 128 + ct * 64 + c] = v;
        }
    }
}

// out[:, :, 0, :] = Phi(zero block) == 0 exactly.
__global__ void zero_slot0_kernel(float* __restrict__ out) {
    int i = blockIdx.x * blockDim.x + threadIdx.x;   // 32*128 = 4096 elems
    int bh = i >> 7;
    int d  = i & 127;
    out[bh * 65536 + d] = 0.0f;
}

extern "C" void kernel_launch(void* const* d_in, const int* in_sizes, int n_in,
                              void* d_out, int out_size) {
    const float* kin   = (const float*)d_in[0];
    const float* pe    = (const float*)d_in[1];
    const float* wdown = (const float*)d_in[2];
    const float* wstop = (const float*)d_in[3];
    float* out = (float*)d_out;

    cudaFuncSetAttribute(compressor_kernel,
                         cudaFuncAttributeMaxDynamicSharedMemorySize,
                         SMEM_BYTES);

    zero_slot0_kernel<<<16, 256>>>(out);
    // 2*16*511 = 16352 windows, 8 per CTA -> 2044 CTAs
    compressor_kernel<<<2044, NTH, SMEM_BYTES>>>(kin, pe, wdown, wstop, out);
}

// round 2
// speedup vs baseline: 3.8665x; 3.8665x over previous
#include <cuda_runtime.h>

// Compressor_86174223827251 — fused fp32, conflict-free smem, f32x2 FMA.
//
// k[2,16,8192,128] f32, pe[32,128], w_down[5,128,256], w_stop[128,128]
// 511 windows/(b,h), stride 16, window 32. Output [2,16,512,128] (slot 0 = 0).
//
// One CTA (512 thr) = 8 windows fused in SMEM:
//   actA [8][32][128] f32 (128 KB), actB [8][16][128] (64 KB), wq tile (32 KB)
// Warp tile: RPW rows x 64 cols; x loads are lane-uniform broadcasts,
// weight tile pre-transposed to [kq][c][4] so lanes read consecutive 16B.
// Weight tiles (22 x 32KB) laid out in consumption order in a __device__
// buffer by a prep kernel; register-prefetched across syncthreads.

#define NW 8
#define NTH 512
#define SMEM_BYTES 229376   // 57344 floats

// __device__ scratch: 23 tiles of 8192 floats (22 used + 1 dummy prefetch pad)
__device__ float g_w_all[23 * 8192];

__device__ __forceinline__ void ffma2(unsigned long long &d,
                                      unsigned long long a,
                                      unsigned long long b) {
    asm("fma.rn.f32x2 %0, %1, %2, %0;" : "+l"(d) : "l"(a), "l"(b));
}
__device__ __forceinline__ float acc_sum(unsigned long long a) {
    float2 f = *reinterpret_cast<float2*>(&a);
    return f.x + f.y;
}
__device__ __forceinline__ float silu_f(float v) {
    return v / (1.0f + __expf(-v));
}

// Commit prefetched tile to smem, then prefetch the next 32KB tile.
__device__ __forceinline__ void commit_and_prefetch(float* __restrict__ wq,
                                                    float4 (&pf)[4],
                                                    const float4*& gnext,
                                                    int tid) {
    float4* dst = reinterpret_cast<float4*>(wq);
#pragma unroll
    for (int i = 0; i < 4; i++) dst[tid + i * NTH] = pf[i];
#pragma unroll
    for (int i = 0; i < 4; i++) pf[i] = gnext[tid + i * NTH];
    gnext += 4 * NTH;  // 2048 float4 = 8192 floats
}

// K-chunk GEMM: 32 kq steps (128 K values). Lanes cover 64 cols (2 halves).
// wq layout: [kq][c][4] floats (c in [0,64)). x rows broadcast per row.
template<int RPW>
__device__ __forceinline__ void gemm32(const float* const (&xr)[RPW],
                                       const float* __restrict__ wq,
                                       int lane,
                                       unsigned long long (&acc)[RPW][2]) {
#pragma unroll 2
    for (int kq = 0; kq < 32; kq++) {
        ulonglong2 w0 = *reinterpret_cast<const ulonglong2*>(wq + kq * 256 + lane * 4);
        ulonglong2 w1 = *reinterpret_cast<const ulonglong2*>(wq + kq * 256 + 128 + lane * 4);
#pragma unroll
        for (int r = 0; r < RPW; r++) {
            ulonglong2 xv = *reinterpret_cast<const ulonglong2*>(xr[r] + kq * 4);
            ffma2(acc[r][0], xv.x, w0.x);
            ffma2(acc[r][0], xv.y, w0.y);
            ffma2(acc[r][1], xv.x, w1.x);
            ffma2(acc[r][1], xv.y, w1.y);
        }
    }
}

// One merge stage. inB: [NW][2*Rout][128] compact, outB: [NW][Rout][128].
template<int RPW, int LGROUT>
__device__ __forceinline__ void run_stage(const float* __restrict__ inB,
                                          float* __restrict__ outB,
                                          float* __restrict__ wq,
                                          float4 (&pf)[4],
                                          const float4*& gnext,
                                          int tid) {
    constexpr int Rout = 1 << LGROUT;
    constexpr int Rin  = 2 * Rout;
    const int warp = tid >> 5, lane = tid & 31;
    const int rowBase = warp * RPW;
    const bool active = rowBase < NW * Rout;

#pragma unroll
    for (int ct = 0; ct < 2; ct++) {
        unsigned long long acc[RPW][2];
#pragma unroll
        for (int r = 0; r < RPW; r++) { acc[r][0] = 0ull; acc[r][1] = 0ull; }

#pragma unroll
        for (int kc = 0; kc < 2; kc++) {
            __syncthreads();                      // prior compute done w/ wq
            commit_and_prefetch(wq, pf, gnext, tid);
            __syncthreads();
            if (active) {
                const float* xr[RPW];
#pragma unroll
                for (int r = 0; r < RPW; r++) {
                    int g  = rowBase + r;
                    int wi = g >> LGROUT;
                    int lr = g & (Rout - 1);
                    xr[r] = inB + (wi * Rin + 2 * lr + kc) * 128;
                }
                gemm32<RPW>(xr, wq, lane, acc);
            }
        }
        if (active) {
#pragma unroll
            for (int r = 0; r < RPW; r++) {
                int g  = rowBase + r;
                int wi = g >> LGROUT;
                int lr = g & (Rout - 1);
                float* o = outB + (wi * Rout + lr) * 128 + ct * 64;
                o[lane]      = silu_f(acc_sum(acc[r][0]));
                o[32 + lane] = silu_f(acc_sum(acc[r][1]));
            }
        }
    }
}

__global__ void __launch_bounds__(NTH, 1)
compressor_kernel(const float* __restrict__ kin,
                  const float* __restrict__ pe,
                  float* __restrict__ out) {
    extern __shared__ float smem[];
    float* actA = smem;                 // [8][32][128] = 32768
    float* actB = smem + 32768;         // [8][16][128] = 16384
    float* wq   = smem + 49152;         // [32][64][4]  =  8192

    const int tid = threadIdx.x;
    const int gbase = blockIdx.x * NW;

    // ---- gather: actA[wi][row][d] = k[bh, 16*j + row, d] + pe[row][d] ----
    for (int i = tid; i < NW * 32 * 128 / 4; i += NTH) {
        int wi  = i >> 10;
        int rem = i & 1023;
        int row = rem >> 5;
        int dq  = rem & 31;
        int g   = gbase + wi;
        int bh  = g / 511;
        int j   = g - bh * 511;
        const float4 kv = *reinterpret_cast<const float4*>(
            kin + ((size_t)bh * 8192 + 16 * j + row) * 128 + dq * 4);
        const float4 pv = *reinterpret_cast<const float4*>(pe + row * 128 + dq * 4);
        float4 o;
        o.x = kv.x + pv.x; o.y = kv.y + pv.y;
        o.z = kv.z + pv.z; o.w = kv.w + pv.w;
        *reinterpret_cast<float4*>(actA + wi * 4096 + row * 128 + dq * 4) = o;
    }

    // ---- prime the weight prefetch pipeline (tile 0) ----
    float4 pf[4];
    const float4* gbaseW = reinterpret_cast<const float4*>(g_w_all);
#pragma unroll
    for (int i = 0; i < 4; i++) pf[i] = gbaseW[tid + i * NTH];
    const float4* gnext = gbaseW + 4 * NTH;   // tile 1

    // ---- 5 merge stages (ping-pong actA <-> actB) ----
    run_stage<8, 4>(actA, actB, wq, pf, gnext, tid);  // s0: 128 rows
    run_stage<4, 3>(actB, actA, wq, pf, gnext, tid);  // s1:  64 rows
    run_stage<2, 2>(actA, actB, wq, pf, gnext, tid);  // s2:  32 rows
    run_stage<1, 1>(actB, actA, wq, pf, gnext, tid);  // s3:  16 rows
    run_stage<1, 0>(actA, actB, wq, pf, gnext, tid);  // s4:   8 rows

    // ---- stop projection: actB[wi][0][:] @ w_stop^T (K=128, no silu) ----
    {
        const int warp = tid >> 5, lane = tid & 31;
        const bool active = warp < NW;
#pragma unroll
        for (int ct = 0; ct < 2; ct++) {
            unsigned long long acc[1][2];
            acc[0][0] = 0ull; acc[0][1] = 0ull;
            __syncthreads();
            commit_and_prefetch(wq, pf, gnext, tid);  // last iter reads pad tile
            __syncthreads();
            if (active) {
                const float* xr[1] = { actB + warp * 128 };
                gemm32<1>(xr, wq, lane, acc);
                int g  = gbase + warp;
                int bh = g / 511;
                int j  = g - bh * 511;
                float* o = out + bh * 65536 + (1 + j) * 128 + ct * 64;
                o[lane]      = acc_sum(acc[0][0]);
                o[32 + lane] = acc_sum(acc[0][1]);
            }
        }
    }
}

// Prep: transpose weights into consumption-ordered tiles.
// Tile t<20: s=t>>2, ct=(t>>1)&1, kc=t&1 ; tile 20/21: w_stop halves.
// Tile layout: [(kq*64 + c)*4 + j], value = W[o = ct*64+c][i = kc*128+kq*4+j]
__global__ void prep_weights_kernel(const float* __restrict__ wdown,
                                    const float* __restrict__ wstop) {
    int idx = blockIdx.x * blockDim.x + threadIdx.x;   // 22*8192 total
    if (idx >= 22 * 8192) return;
    int t  = idx >> 13;
    int r  = idx & 8191;
    int kq = r >> 8;
    int c  = (r >> 2) & 63;
    int j  = r & 3;
    float v;
    if (t < 20) {
        int s  = t >> 2;
        int ct = (t >> 1) & 1;
        int kc = t & 1;
        v = wdown[s * 32768 + (ct * 64 + c) * 256 + kc * 128 + kq * 4 + j];
    } else {
        int ct = t & 1;
        v = wstop[(ct * 64 + c) * 128 + kq * 4 + j];
    }
    g_w_all[idx] = v;
}

// out[:, :, 0, :] = Phi(zero block) == 0 exactly.
__global__ void zero_slot0_kernel(float* __restrict__ out) {
    int i = blockIdx.x * blockDim.x + threadIdx.x;   // 32*128 = 4096
    int bh = i >> 7;
    int d  = i & 127;
    out[bh * 65536 + d] = 0.0f;
}

extern "C" void kernel_launch(void* const* d_in, const int* in_sizes, int n_in,
                              void* d_out, int out_size) {
    const float* kin   = (const float*)d_in[0];
    const float* pe    = (const float*)d_in[1];
    const float* wdown = (const float*)d_in[2];
    const float* wstop = (const float*)d_in[3];
    float* out = (float*)d_out;

    cudaFuncSetAttribute(compressor_kernel,
                         cudaFuncAttributeMaxDynamicSharedMemorySize,
                         SMEM_BYTES);

    prep_weights_kernel<<<(22 * 8192 + 255) / 256, 256>>>(wdown, wstop);
    zero_slot0_kernel<<<16, 256>>>(out);
    compressor_kernel<<<2044, NTH, SMEM_BYTES>>>(kin, pe, out);
}

// round 7
// speedup vs baseline: 8.0046x; 2.0702x over previous
#include <cuda_runtime.h>
#include <cuda_bf16.h>
#include <cstdint>

// Compressor — mma.sync bf16 3-pass split (x*w ~= xh*wh + xh*wl + xl*wh).
// A = activations [rows][K] bf16 (hi/lo), B = weights [n][k] bf16 (hi/lo).
#define NTH 256

// smem byte offsets (x rows padded to 528 B, W rows to 80 B)
#define XAH 0
#define XAL 67584
#define XBH 135168
#define XBL 168960
#define WHO 202752
#define WLO 212992
#define SMEM_BYTES 223232

// Weights pre-split, consumption-ordered: 44 chunks x 4096 u32 (+1 pad chunk).
// chunk = [hi: 2048 words [n=128][kw=16]] [lo: 2048 words]
__device__ uint32_t g_wq[184320];

static __device__ __forceinline__ uint32_t smem_u32(const void* p){
    uint32_t a;
    asm("{ .reg .u64 t; cvta.to.shared.u64 t, %1; cvt.u32.u64 %0, t; }" : "=r"(a) : "l"(p));
    return a;
}
static __device__ __forceinline__ void ldsm4(uint32_t* r, uint32_t a){
    asm volatile("ldmatrix.sync.aligned.m8n8.x4.shared.b16 {%0,%1,%2,%3}, [%4];"
        : "=r"(r[0]),"=r"(r[1]),"=r"(r[2]),"=r"(r[3]) : "r"(a));
}
static __device__ __forceinline__ void ldsm2(uint32_t* r, uint32_t a){
    asm volatile("ldmatrix.sync.aligned.m8n8.x2.shared.b16 {%0,%1}, [%2];"
        : "=r"(r[0]),"=r"(r[1]) : "r"(a));
}
static __device__ __forceinline__ void mma16816(float* c, const uint32_t* a,
                                                const uint32_t* b){
    asm volatile("mma.sync.aligned.m16n8k16.row.col.f32.bf16.bf16.f32 "
        "{%0,%1,%2,%3}, {%4,%5,%6,%7}, {%8,%9}, {%0,%1,%2,%3};"
        : "+f"(c[0]),"+f"(c[1]),"+f"(c[2]),"+f"(c[3])
        : "r"(a[0]),"r"(a[1]),"r"(a[2]),"r"(a[3]), "r"(b[0]),"r"(b[1]));
}
static __device__ __forceinline__ uint32_t pack2(float a, float b){
    __nv_bfloat162 t = __floats2bfloat162_rn(a, b);
    return *reinterpret_cast<uint32_t*>(&t);
}
static __device__ __forceinline__ float bfr(float v){
    return __bfloat162float(__float2bfloat16(v));
}
static __device__ __forceinline__ float silu_f(float v){
    return v / (1.0f + __expf(-v));
}

// MODE: 0 = paired epilogue (silu, write rr=r>>1, cc=(r&1)*128+n)
//       1 = s4 epilogue (silu, rr=r, cc=n, rows<8 only)
//       2 = stop (no silu, gmem, rows<8 only)
template<int NT, int MODE>
static __device__ __forceinline__ void run_stage(
        char* smem, int xin_h, int xin_l, int xo_h, int xo_l,
        float* __restrict__ out, int gbase,
        uint4* const (&wdst)[4], uint4 (&pf)[4], const uint4*& gnext,
        int mrow0, int cbase, int nchunks)
{
    const int tid = threadIdx.x, lane = tid & 31;
    const uint32_t xh_u = smem_u32(smem + xin_h);
    const uint32_t xl_u = smem_u32(smem + xin_l);
    const uint32_t wh_u = smem_u32(smem + WHO);
    const uint32_t wl_u = smem_u32(smem + WLO);

    float c[NT][4];
#pragma unroll
    for (int nt = 0; nt < NT; nt++)
#pragma unroll
        for (int q = 0; q < 4; q++) c[nt][q] = 0.0f;

    for (int ch = 0; ch < nchunks; ch++){
        __syncthreads();
#pragma unroll
        for (int i = 0; i < 4; i++) *wdst[i] = pf[i];
#pragma unroll
        for (int i = 0; i < 4; i++) pf[i] = gnext[tid + i * 256];
        gnext += 1024;
        __syncthreads();

#pragma unroll
        for (int ks = 0; ks < 2; ks++){
            const int kg = ch * 32 + ks * 16;
            const uint32_t aoff = (uint32_t)(mrow0 + (lane & 15)) * 528u
                                + (uint32_t)(kg + ((lane >> 4) << 3)) * 2u;
            uint32_t ah[4], al[4];
            ldsm4(ah, xh_u + aoff);
            ldsm4(al, xl_u + aoff);
            const uint32_t bro = (uint32_t)(cbase + (lane & 7)) * 80u
                               + (uint32_t)(ks * 16 + ((lane >> 3) & 1) * 8) * 2u;
#pragma unroll
            for (int nt = 0; nt < NT; nt++){
                const uint32_t bo = bro + (uint32_t)nt * 640u;  // 8 rows * 80B
                uint32_t bh[2], bl[2];
                ldsm2(bh, wh_u + bo);
                ldsm2(bl, wl_u + bo);
                mma16816(c[nt], ah, bh);
                mma16816(c[nt], ah, bl);
                mma16816(c[nt], al, bh);
            }
        }
    }

    // epilogue
    const int t4 = lane >> 2, tn = lane & 3;
#pragma unroll
    for (int nt = 0; nt < NT; nt++){
        const int n0 = cbase + nt * 8 + tn * 2;
        const int r1 = mrow0 + t4;
        if (MODE == 2){
            const int g = gbase + r1, b_ = g / 511, j = g - b_ * 511;
            float2 v; v.x = c[nt][0]; v.y = c[nt][1];
            *reinterpret_cast<float2*>(out + b_ * 65536 + (1 + j) * 128 + n0) = v;
        } else {
            float v0 = silu_f(c[nt][0]), v1 = silu_f(c[nt][1]);
            float h0 = bfr(v0), h1 = bfr(v1);
            int rr = (MODE == 0) ? (r1 >> 1) : r1;
            int cc = (MODE == 0) ? ((r1 & 1) * 128 + n0) : n0;
            uint32_t off = (uint32_t)rr * 528u + (uint32_t)cc * 2u;
            *reinterpret_cast<uint32_t*>(smem + xo_h + off) = pack2(h0, h1);
            *reinterpret_cast<uint32_t*>(smem + xo_l + off) = pack2(v0 - h0, v1 - h1);
            if (MODE == 0){
                const int r2 = r1 + 8;
                float w0 = silu_f(c[nt][2]), w1 = silu_f(c[nt][3]);
                float g0 = bfr(w0), g1 = bfr(w1);
                rr = r2 >> 1; cc = (r2 & 1) * 128 + n0;
                off = (uint32_t)rr * 528u + (uint32_t)cc * 2u;
                *reinterpret_cast<uint32_t*>(smem + xo_h + off) = pack2(g0, g1);
                *reinterpret_cast<uint32_t*>(smem + xo_l + off) = pack2(w0 - g0, w1 - g1);
            }
        }
    }
}

__global__ void __launch_bounds__(NTH, 1)
comp_kernel(const float* __restrict__ kin, const float* __restrict__ pe,
            float* __restrict__ out){
    extern __shared__ char smem[];
    const int tid = threadIdx.x, wid = tid >> 5;
    const int gbase = blockIdx.x * 8;

    // precomputed W STS targets (same decode every chunk)
    uint4* wdst[4];
#pragma unroll
    for (int i = 0; i < 4; i++){
        int w0 = (tid + i * 256) * 4;
        int buf = w0 >> 11, ww = w0 & 2047;
        wdst[i] = reinterpret_cast<uint4*>(
            smem + (buf ? WLO : WHO) + (ww >> 4) * 80 + (ww & 15) * 4);
    }

    // gather: xA[n=16wi+lr][h*128+f] = k[bh][16j+2lr+h][f] + pe[2lr+h][f]
    for (int it = 0; it < 32; it++){
        int i = tid + it * NTH;
        int fq = i & 31, h = (i >> 5) & 1, n = i >> 6;
        int wi = n >> 4, lr = n & 15, r = 2 * lr + h;
        int g = gbase + wi, b_ = g / 511, j = g - b_ * 511;
        const float4 kv = *reinterpret_cast<const float4*>(
            kin + ((size_t)b_ * 8192 + 16 * j + r) * 128 + fq * 4);
        const float4 pv = *reinterpret_cast<const float4*>(pe + r * 128 + fq * 4);
        float x0 = kv.x + pv.x, x1 = kv.y + pv.y;
        float x2 = kv.z + pv.z, x3 = kv.w + pv.w;
        float h0 = bfr(x0), h1 = bfr(x1), h2 = bfr(x2), h3 = bfr(x3);
        uint2 hh, ll;
        hh.x = pack2(h0, h1);           hh.y = pack2(h2, h3);
        ll.x = pack2(x0 - h0, x1 - h1); ll.y = pack2(x2 - h2, x3 - h3);
        uint32_t off = (uint32_t)n * 528u + (uint32_t)h * 256u + (uint32_t)fq * 8u;
        *reinterpret_cast<uint2*>(smem + XAH + off) = hh;
        *reinterpret_cast<uint2*>(smem + XAL + off) = ll;
    }

    // prime W prefetch
    uint4 pf[4];
    const uint4* gnext = reinterpret_cast<const uint4*>(g_wq);
#pragma unroll
    for (int i = 0; i < 4; i++) pf[i] = gnext[tid + i * 256];
    gnext += 1024;

    run_stage<16,0>(smem, XAH, XAL, XBH, XBL, out, gbase, wdst, pf, gnext,
                    wid * 16, 0, 8);
    run_stage< 8,0>(smem, XBH, XBL, XAH, XAL, out, gbase, wdst, pf, gnext,
                    (wid >> 1) * 16, (wid & 1) * 64, 8);
    run_stage< 4,0>(smem, XAH, XAL, XBH, XBL, out, gbase, wdst, pf, gnext,
                    (wid >> 2) * 16, (wid & 3) * 32, 8);
    run_stage< 2,0>(smem, XBH, XBL, XAH, XAL, out, gbase, wdst, pf, gnext,
                    0, wid * 16, 8);
    run_stage< 2,1>(smem, XAH, XAL, XBH, XBL, out, gbase, wdst, pf, gnext,
                    0, wid * 16, 8);
    run_stage< 2,2>(smem, XBH, XBL, 0, 0, out, gbase, wdst, pf, gnext,
                    0, wid * 16, 4);
}

// Pre-split weights to bf16 hi/lo words in exact consumption order.
__global__ void prep_kernel(const float* __restrict__ wdown,
                            const float* __restrict__ wstop){
    int idx = blockIdx.x * blockDim.x + threadIdx.x;
    if (idx >= 184320) return;
    if (idx >= 180224){ g_wq[idx] = 0u; return; }
    int buf, n, i;
    const float* src;
    if (idx < 163840){
        int s = idx >> 15, rem = idx & 32767;
        int c = rem >> 12; buf = (rem >> 11) & 1;
        int w = rem & 2047; n = w >> 4; i = c * 32 + (w & 15) * 2;
        src = wdown + s * 32768 + n * 256 + i;
    } else {
        int r2 = idx - 163840;
        int c = r2 >> 12; buf = (r2 >> 11) & 1;
        int w = r2 & 2047; n = w >> 4; i = c * 32 + (w & 15) * 2;
        src = wstop + n * 128 + i;
    }
    float a = src[0], b = src[1];
    if (buf){
        a -= __bfloat162float(__float2bfloat16(a));
        b -= __bfloat162float(__float2bfloat16(b));
    }
    __nv_bfloat162 t = __floats2bfloat162_rn(a, b);
    g_wq[idx] = *reinterpret_cast<uint32_t*>(&t);
}

__global__ void zero_slot0_kernel(float* __restrict__ out){
    int i = blockIdx.x * blockDim.x + threadIdx.x;   // 4096
    out[(i >> 7) * 65536 + (i & 127)] = 0.0f;
}

extern "C" void kernel_launch(void* const* d_in, const int* in_sizes, int n_in,
                              void* d_out, int out_size){
    const float* kin   = (const float*)d_in[0];
    const float* pe    = (const float*)d_in[1];
    const float* wdown = (const float*)d_in[2];
    const float* wstop = (const float*)d_in[3];
    float* out = (float*)d_out;

    cudaFuncSetAttribute(comp_kernel,
                         cudaFuncAttributeMaxDynamicSharedMemorySize, SMEM_BYTES);
    prep_kernel<<<720, 256>>>(wdown, wstop);
    zero_slot0_kernel<<<16, 256>>>(out);
    comp_kernel<<<2044, NTH, SMEM_BYTES>>>(kin, pe, out);
}

// round 8
// speedup vs baseline: 10.3788x; 1.2966x over previous
#include <cuda_runtime.h>
#include <cuda_bf16.h>
#include <cstdint>

// Compressor — mma.sync bf16 3-pass split + cp.async double-buffered weights.
// A = activations [rows][K] bf16 hi/lo (512B rows, XOR-swizzled),
// B = weights [n][k] bf16 hi/lo (64B rows, SW64-swizzled, 2 smem buffers).
#define NTH 256

// smem byte offsets
#define XAH 0
#define XAL 65536
#define XBH 131072
#define XBL 163840
#define WB0 196608
#define WB1 212992
#define SMEM_BYTES 229376

// Weights pre-split, consumption-ordered: 44 chunks x 4096 u32 + 2 pad chunks.
// chunk = [hi: 2048 words [n=128][kw=16]] [lo: 2048 words]  (32 k-values)
__device__ uint32_t g_wq[188416];

static __device__ __forceinline__ uint32_t smem_u32(const void* p){
    uint32_t a;
    asm("{ .reg .u64 t; cvta.to.shared.u64 t, %1; cvt.u32.u64 %0, t; }" : "=r"(a) : "l"(p));
    return a;
}
static __device__ __forceinline__ uint32_t swzA(uint32_t o){ return o ^ ((o >> 5) & 0x70u); }
static __device__ __forceinline__ uint32_t swzW(uint32_t o){ return o ^ ((o >> 3) & 0x30u); }

static __device__ __forceinline__ void ldsm4(uint32_t* r, uint32_t a){
    asm volatile("ldmatrix.sync.aligned.m8n8.x4.shared.b16 {%0,%1,%2,%3}, [%4];"
        : "=r"(r[0]),"=r"(r[1]),"=r"(r[2]),"=r"(r[3]) : "r"(a));
}
static __device__ __forceinline__ void mma16816(float* c, const uint32_t* a,
                                                const uint32_t* b){
    asm volatile("mma.sync.aligned.m16n8k16.row.col.f32.bf16.bf16.f32 "
        "{%0,%1,%2,%3}, {%4,%5,%6,%7}, {%8,%9}, {%0,%1,%2,%3};"
        : "+f"(c[0]),"+f"(c[1]),"+f"(c[2]),"+f"(c[3])
        : "r"(a[0]),"r"(a[1]),"r"(a[2]),"r"(a[3]), "r"(b[0]),"r"(b[1]));
}
static __device__ __forceinline__ void cp16(uint32_t d, const void* g){
    asm volatile("cp.async.cg.shared.global [%0], [%1], 16;" :: "r"(d),"l"(g) : "memory");
}
#define CPCOMMIT() asm volatile("cp.async.commit_group;":::"memory")
#define CPWAIT1()  asm volatile("cp.async.wait_group 1;":::"memory")
#define CPWAIT0()  asm volatile("cp.async.wait_group 0;":::"memory")

static __device__ __forceinline__ uint32_t pack2(float a, float b){
    __nv_bfloat162 t = __floats2bfloat162_rn(a, b);
    return *reinterpret_cast<uint32_t*>(&t);
}
static __device__ __forceinline__ float bfr(float v){
    return __bfloat162float(__float2bfloat16(v));
}
static __device__ __forceinline__ float silu_f(float v){
    return v / (1.0f + __expf(-v));
}

struct WPipe {
    uint32_t wb0, wb1;
    uint32_t dstoff[4];
    int ch;
    __device__ __forceinline__ void issue(int c){
        uint32_t b = (c & 1) ? wb1 : wb0;
        const uint4* s = reinterpret_cast<const uint4*>(g_wq) + c * 1024 + threadIdx.x;
#pragma unroll
        for (int i = 0; i < 4; i++) cp16(b + dstoff[i], s + i * 256);
        CPCOMMIT();
    }
};

// MODE: 0 = paired epilogue (silu, rr=r>>1, cc=(r&1)*128+n)
//       1 = s4 epilogue (silu, rr=r, cc=n, rows<8 only)
//       2 = stop (no silu, gmem, rows<8 only)
template<int NT, int MODE>
static __device__ __forceinline__ void run_stage(
        char* smem, int xin_h, int xin_l, int xo_h, int xo_l,
        float* __restrict__ out, int gbase, WPipe& wp,
        int mrow0, int cbase, int nchunks)
{
    const int lane = threadIdx.x & 31;
    const uint32_t xh_u = smem_u32(smem + xin_h);
    const uint32_t xl_u = smem_u32(smem + xin_l);

    float c[NT][4];
#pragma unroll
    for (int nt = 0; nt < NT; nt++)
#pragma unroll
        for (int q = 0; q < 4; q++) c[nt][q] = 0.0f;

    for (int cc = 0; cc < nchunks; cc++){
        CPWAIT1();
        __syncthreads();
        const uint32_t wh_u = (wp.ch & 1) ? wp.wb1 : wp.wb0;   // hi half
        // B lane address (swizzle invariant across ntp/half offsets)
        const uint32_t brow = (uint32_t)(cbase + ((lane >> 4) << 3) + (lane & 7));
#pragma unroll
        for (int ks = 0; ks < 2; ks++){
            const int kg = cc * 32 + ks * 16;
            const uint32_t aoff = swzA((uint32_t)(mrow0 + (lane & 15)) * 512u
                                     + (uint32_t)(kg + ((lane >> 4) << 3)) * 2u);
            uint32_t ah[4], al[4];
            ldsm4(ah, xh_u + aoff);
            ldsm4(al, xl_u + aoff);
            const uint32_t bo0 = swzW(brow * 64u
                                + (uint32_t)(ks * 32 + ((lane >> 3) & 1) * 16));
#pragma unroll
            for (int ntp = 0; ntp < NT / 2; ntp++){
                const uint32_t bo = bo0 + (uint32_t)ntp * 1024u;  // +16 rows
                uint32_t bh[4], bl[4];
                ldsm4(bh, wh_u + bo);
                ldsm4(bl, wh_u + bo + 8192u);
                mma16816(c[ntp*2],   ah, bh);
                mma16816(c[ntp*2],   ah, bl);
                mma16816(c[ntp*2],   al, bh);
                mma16816(c[ntp*2+1], ah, bh + 2);
                mma16816(c[ntp*2+1], ah, bl + 2);
                mma16816(c[ntp*2+1], al, bh + 2);
            }
        }
        __syncthreads();
        wp.issue(wp.ch + 2);
        wp.ch++;
    }

    // epilogue
    const int t4 = lane >> 2, tn = lane & 3;
#pragma unroll
    for (int nt = 0; nt < NT; nt++){
        const int n0 = cbase + nt * 8 + tn * 2;
        const int r1 = mrow0 + t4;
        if (MODE == 2){
            const int g = gbase + r1, b_ = g / 511, j = g - b_ * 511;
            float2 v; v.x = c[nt][0]; v.y = c[nt][1];
            *reinterpret_cast<float2*>(out + b_ * 65536 + (1 + j) * 128 + n0) = v;
        } else {
            float v0 = silu_f(c[nt][0]), v1 = silu_f(c[nt][1]);
            float h0 = bfr(v0), h1 = bfr(v1);
            int rr = (MODE == 0) ? (r1 >> 1) : r1;
            int cc2 = (MODE == 0) ? ((r1 & 1) * 128 + n0) : n0;
            uint32_t off = swzA((uint32_t)rr * 512u + (uint32_t)cc2 * 2u);
            *reinterpret_cast<uint32_t*>(smem + xo_h + off) = pack2(h0, h1);
            *reinterpret_cast<uint32_t*>(smem + xo_l + off) = pack2(v0 - h0, v1 - h1);
            if (MODE == 0){
                const int r2 = r1 + 8;
                float w0 = silu_f(c[nt][2]), w1 = silu_f(c[nt][3]);
                float g0 = bfr(w0), g1 = bfr(w1);
                rr = r2 >> 1; cc2 = (r2 & 1) * 128 + n0;
                off = swzA((uint32_t)rr * 512u + (uint32_t)cc2 * 2u);
                *reinterpret_cast<uint32_t*>(smem + xo_h + off) = pack2(g0, g1);
                *reinterpret_cast<uint32_t*>(smem + xo_l + off) = pack2(w0 - g0, w1 - g1);
            }
        }
    }
}

__global__ void __launch_bounds__(NTH, 1)
comp_kernel(const float* __restrict__ kin, const float* __restrict__ pe,
            float* __restrict__ out){
    extern __shared__ char smem[];
    const int tid = threadIdx.x, wid = tid >> 5;
    const int gbase = blockIdx.x * 8;

    WPipe wp;
    wp.wb0 = smem_u32(smem + WB0);
    wp.wb1 = smem_u32(smem + WB1);
    wp.ch = 0;
#pragma unroll
    for (int i = 0; i < 4; i++){
        int e = tid + i * 256;
        int half = e >> 9, rem = e & 511;
        int n = rem >> 2, u = rem & 3;
        wp.dstoff[i] = (uint32_t)(half * 8192) + swzW((uint32_t)(n * 64 + u * 16));
    }
    wp.issue(0);
    wp.issue(1);

    // gather: xA[n=16wi+lr][h*128+f] = k[bh][16j+2lr+h][f] + pe[2lr+h][f]
    for (int it = 0; it < 32; it++){
        int i = tid + it * NTH;
        int fq = i & 31, h = (i >> 5) & 1, n = i >> 6;
        int wi = n >> 4, lr = n & 15, r = 2 * lr + h;
        int g = gbase + wi, b_ = g / 511, j = g - b_ * 511;
        const float4 kv = *reinterpret_cast<const float4*>(
            kin + ((size_t)b_ * 8192 + 16 * j + r) * 128 + fq * 4);
        const float4 pv = *reinterpret_cast<const float4*>(pe + r * 128 + fq * 4);
        float x0 = kv.x + pv.x, x1 = kv.y + pv.y;
        float x2 = kv.z + pv.z, x3 = kv.w + pv.w;
        float h0 = bfr(x0), h1 = bfr(x1), h2 = bfr(x2), h3 = bfr(x3);
        uint2 hh, ll;
        hh.x = pack2(h0, h1);           hh.y = pack2(h2, h3);
        ll.x = pack2(x0 - h0, x1 - h1); ll.y = pack2(x2 - h2, x3 - h3);
        uint32_t off = swzA((uint32_t)n * 512u + (uint32_t)h * 256u + (uint32_t)fq * 8u);
        *reinterpret_cast<uint2*>(smem + XAH + off) = hh;
        *reinterpret_cast<uint2*>(smem + XAL + off) = ll;
    }

    run_stage<16,0>(smem, XAH, XAL, XBH, XBL, out, gbase, wp, wid * 16, 0, 8);
    run_stage< 8,0>(smem, XBH, XBL, XAH, XAL, out, gbase, wp,
                    (wid >> 1) * 16, (wid & 1) * 64, 8);
    run_stage< 4,0>(smem, XAH, XAL, XBH, XBL, out, gbase, wp,
                    (wid >> 2) * 16, (wid & 3) * 32, 8);
    run_stage< 2,0>(smem, XBH, XBL, XAH, XAL, out, gbase, wp, 0, wid * 16, 8);
    run_stage< 2,1>(smem, XAH, XAL, XBH, XBL, out, gbase, wp, 0, wid * 16, 8);
    run_stage< 2,2>(smem, XBH, XBL, 0, 0, out, gbase, wp, 0, wid * 16, 4);

    CPWAIT0();   // drain pad-chunk groups before exit
}

// Pre-split weights to bf16 hi/lo words in exact consumption order.
__global__ void prep_kernel(const float* __restrict__ wdown,
                            const float* __restrict__ wstop){
    int idx = blockIdx.x * blockDim.x + threadIdx.x;
    if (idx >= 188416) return;
    if (idx >= 180224){ g_wq[idx] = 0u; return; }
    int buf, n, i;
    const float* src;
    if (idx < 163840){
        int s = idx >> 15, rem = idx & 32767;
        int c = rem >> 12; buf = (rem >> 11) & 1;
        int w = rem & 2047; n = w >> 4; i = c * 32 + (w & 15) * 2;
        src = wdown + s * 32768 + n * 256 + i;
    } else {
        int r2 = idx - 163840;
        int c = r2 >> 12; buf = (r2 >> 11) & 1;
        int w = r2 & 2047; n = w >> 4; i = c * 32 + (w & 15) * 2;
        src = wstop + n * 128 + i;
    }
    float a = src[0], b = src[1];
    if (buf){
        a -= __bfloat162float(__float2bfloat16(a));
        b -= __bfloat162float(__float2bfloat16(b));
    }
    __nv_bfloat162 t = __floats2bfloat162_rn(a, b);
    g_wq[idx] = *reinterpret_cast<uint32_t*>(&t);
}

__global__ void zero_slot0_kernel(float* __restrict__ out){
    int i = blockIdx.x * blockDim.x + threadIdx.x;   // 4096
    out[(i >> 7) * 65536 + (i & 127)] = 0.0f;
}

extern "C" void kernel_launch(void* const* d_in, const int* in_sizes, int n_in,
                              void* d_out, int out_size){
    const float* kin   = (const float*)d_in[0];
    const float* pe    = (const float*)d_in[1];
    const float* wdown = (const float*)d_in[2];
    const float* wstop = (const float*)d_in[3];
    float* out = (float*)d_out;

    cudaFuncSetAttribute(comp_kernel,
                         cudaFuncAttributeMaxDynamicSharedMemorySize, SMEM_BYTES);
    prep_kernel<<<736, 256>>>(wdown, wstop);
    zero_slot0_kernel<<<16, 256>>>(out);
    comp_kernel<<<2044, NTH, SMEM_BYTES>>>(kin, pe, out);
}

// round 10
// speedup vs baseline: 10.9906x; 1.0589x over previous
#include <cuda_runtime.h>
#include <cuda_bf16.h>
#include <cstdint>

// Compressor — mma.sync bf16 3-pass split, two-kernel hierarchy.
// Kernel A: stages 0-2, 8 windows/CTA.  Kernel B: stages 3-5, 32 windows/CTA.
#define NTH 256

// Kernel A smem offsets (rows 512B, XOR swizzle; W rows 64B SW64)
#define XAH 0
#define XAL 65536
#define XBH 131072
#define XBL 163840
#define WA0 196608
#define WA1 212992
#define SMEM_A 229376
// Kernel B smem offsets
#define BXAH 0
#define BXAL 32768
#define BXBH 65536
#define BXBL 81920
#define BX2H 98304
#define BX2L 114688
#define BW0  131072
#define SMEM_B 196608

// Weights pre-split, consumption-ordered: 44 chunks x 4096 u32 + 3 pad chunks.
__device__ uint32_t g_wq[192512];
// Stage2 -> stage3 handoff: [hi/lo][32704 rows][128 u32 (256 bf16)]
__device__ uint32_t g_mid[2][4186112];

static __device__ __forceinline__ uint32_t smem_u32(const void* p){
    uint32_t a;
    asm("{ .reg .u64 t; cvta.to.shared.u64 t, %1; cvt.u32.u64 %0, t; }" : "=r"(a) : "l"(p));
    return a;
}
static __device__ __forceinline__ uint32_t swzA(uint32_t o){ return o ^ ((o >> 5) & 0x70u); }
static __device__ __forceinline__ uint32_t swzW(uint32_t o){ return o ^ ((o >> 3) & 0x30u); }

static __device__ __forceinline__ void ldsm4(uint32_t* r, uint32_t a){
    asm volatile("ldmatrix.sync.aligned.m8n8.x4.shared.b16 {%0,%1,%2,%3}, [%4];"
        : "=r"(r[0]),"=r"(r[1]),"=r"(r[2]),"=r"(r[3]) : "r"(a));
}
static __device__ __forceinline__ void mma16816(float* c, const uint32_t* a,
                                                const uint32_t* b){
    asm volatile("mma.sync.aligned.m16n8k16.row.col.f32.bf16.bf16.f32 "
        "{%0,%1,%2,%3}, {%4,%5,%6,%7}, {%8,%9}, {%0,%1,%2,%3};"
        : "+f"(c[0]),"+f"(c[1]),"+f"(c[2]),"+f"(c[3])
        : "r"(a[0]),"r"(a[1]),"r"(a[2]),"r"(a[3]), "r"(b[0]),"r"(b[1]));
}
static __device__ __forceinline__ void cp16(uint32_t d, const void* g){
    asm volatile("cp.async.cg.shared.global [%0], [%1], 16;" :: "r"(d),"l"(g) : "memory");
}
#define CPCOMMIT() asm volatile("cp.async.commit_group;":::"memory")
#define CPWAIT1()  asm volatile("cp.async.wait_group 1;":::"memory")
#define CPWAIT2()  asm volatile("cp.async.wait_group 2;":::"memory")
#define CPWAIT0()  asm volatile("cp.async.wait_group 0;":::"memory")

static __device__ __forceinline__ uint32_t pack2(float a, float b){
    __nv_bfloat162 t = __floats2bfloat162_rn(a, b);
    return *reinterpret_cast<uint32_t*>(&t);
}
static __device__ __forceinline__ float bfr(float v){
    return __bfloat162float(__float2bfloat16(v));
}
static __device__ __forceinline__ float silu_f(float v){
    return v / (1.0f + __expf(-v));
}

struct WPipe {
    uint32_t wb[4];
    uint32_t dstoff[4];
    int ch;
    __device__ __forceinline__ void init_dst(){
#pragma unroll
        for (int i = 0; i < 4; i++){
            int e = threadIdx.x + i * 256;
            int half = e >> 9, rem = e & 511;
            int n = rem >> 2, u = rem & 3;
            dstoff[i] = (uint32_t)(half * 8192) + swzW((uint32_t)(n * 64 + u * 16));
        }
    }
    __device__ __forceinline__ void issue(int c, int nb){
        uint32_t b = wb[c & (nb - 1)];
        const uint4* s = reinterpret_cast<const uint4*>(g_wq) + c * 1024 + threadIdx.x;
#pragma unroll
        for (int i = 0; i < 4; i++) cp16(b + dstoff[i], s + i * 256);
        CPCOMMIT();
    }
};

// Store one output row (silu'd value pair) to smem in paired/direct layout.
static __device__ __forceinline__ void store_pair_smem(
        char* smem, int xo_h, int xo_l, int rr, int cc2, float v0, float v1){
    float h0 = bfr(v0), h1 = bfr(v1);
    uint32_t off = swzA((uint32_t)rr * 512u + (uint32_t)cc2 * 2u);
    *reinterpret_cast<uint32_t*>(smem + xo_h + off) = pack2(h0, h1);
    *reinterpret_cast<uint32_t*>(smem + xo_l + off) = pack2(v0 - h0, v1 - h1);
}
static __device__ __forceinline__ void store_pair_mid(
        int gbase, int r, int n0, float v0, float v1){
    float h0 = bfr(v0), h1 = bfr(v1);
    int w = gbase + (r >> 2), rl = r & 3;
    int midrow = w * 2 + (rl >> 1);
    int cc2 = (rl & 1) * 128 + n0;
    g_mid[0][midrow * 128 + (cc2 >> 1)] = pack2(h0, h1);
    g_mid[1][midrow * 128 + (cc2 >> 1)] = pack2(v0 - h0, v1 - h1);
}

// MODE: 0 paired->smem (silu); 1 direct rr=r,cc=n ->smem (silu);
//       2 stop->gmem (no silu); 3 paired->g_mid (silu, bf16 hi/lo)
// ALL modes store BOTH D row halves (r1 = mrow0+t4 and r2 = r1+8).
template<int NT, int MODE, int NB>
static __device__ __forceinline__ void run_stage(
        char* smem, int xin_h, int xin_l, int xo_h, int xo_l,
        float* __restrict__ out, int gbase, WPipe& wp,
        int mrow0, int cbase, int nchunks)
{
    const int lane = threadIdx.x & 31;
    const uint32_t xh_u = smem_u32(smem + xin_h);
    const uint32_t xl_u = smem_u32(smem + xin_l);

    float c[NT][4];
#pragma unroll
    for (int nt = 0; nt < NT; nt++)
#pragma unroll
        for (int q = 0; q < 4; q++) c[nt][q] = 0.0f;

    for (int cc = 0; cc < nchunks; cc++){
        if (NB == 2){ CPWAIT1(); __syncthreads(); }
        else        { CPWAIT2(); __syncthreads(); wp.issue(wp.ch + 3, NB); }
        const uint32_t wh_u = wp.wb[wp.ch & (NB - 1)];
        const uint32_t brow = (uint32_t)(cbase + ((lane >> 4) << 3) + (lane & 7));
#pragma unroll
        for (int ks = 0; ks < 2; ks++){
            const int kg = cc * 32 + ks * 16;
            const uint32_t aoff = swzA((uint32_t)(mrow0 + (lane & 15)) * 512u
                                     + (uint32_t)(kg + ((lane >> 4) << 3)) * 2u);
            uint32_t ah[4], al[4];
            ldsm4(ah, xh_u + aoff);
            ldsm4(al, xl_u + aoff);
            const uint32_t bo0 = swzW(brow * 64u
                                + (uint32_t)(ks * 32 + ((lane >> 3) & 1) * 16));
#pragma unroll
            for (int ntp = 0; ntp < NT / 2; ntp++){
                const uint32_t bo = bo0 + (uint32_t)ntp * 1024u;
                uint32_t bh[4], bl[4];
                ldsm4(bh, wh_u + bo);
                ldsm4(bl, wh_u + bo + 8192u);
                mma16816(c[ntp*2],   ah, bh);
                mma16816(c[ntp*2],   ah, bl);
                mma16816(c[ntp*2],   al, bh);
                mma16816(c[ntp*2+1], ah, bh + 2);
                mma16816(c[ntp*2+1], ah, bl + 2);
                mma16816(c[ntp*2+1], al, bh + 2);
            }
        }
        if (NB == 2){ __syncthreads(); wp.issue(wp.ch + 2, NB); }
        wp.ch++;
    }

    const int t4 = lane >> 2, tn = lane & 3;
#pragma unroll
    for (int nt = 0; nt < NT; nt++){
        const int n0 = cbase + nt * 8 + tn * 2;
        const int r1 = mrow0 + t4;
        const int r2 = r1 + 8;
        if (MODE == 2){
            int g = gbase + r1, b_ = g / 511, j = g - b_ * 511;
            float2 v; v.x = c[nt][0]; v.y = c[nt][1];
            *reinterpret_cast<float2*>(out + b_ * 65536 + (1 + j) * 128 + n0) = v;
            g = gbase + r2; b_ = g / 511; j = g - b_ * 511;
            float2 v2; v2.x = c[nt][2]; v2.y = c[nt][3];
            *reinterpret_cast<float2*>(out + b_ * 65536 + (1 + j) * 128 + n0) = v2;
        } else if (MODE == 3){
            store_pair_mid(gbase, r1, n0, silu_f(c[nt][0]), silu_f(c[nt][1]));
            store_pair_mid(gbase, r2, n0, silu_f(c[nt][2]), silu_f(c[nt][3]));
        } else if (MODE == 1){
            store_pair_smem(smem, xo_h, xo_l, r1, n0,
                            silu_f(c[nt][0]), silu_f(c[nt][1]));
            store_pair_smem(smem, xo_h, xo_l, r2, n0,
                            silu_f(c[nt][2]), silu_f(c[nt][3]));
        } else {
            store_pair_smem(smem, xo_h, xo_l, r1 >> 1, (r1 & 1) * 128 + n0,
                            silu_f(c[nt][0]), silu_f(c[nt][1]));
            store_pair_smem(smem, xo_h, xo_l, r2 >> 1, (r2 & 1) * 128 + n0,
                            silu_f(c[nt][2]), silu_f(c[nt][3]));
        }
    }
}

// Kernel A: stages 0-2, 8 windows/CTA.
__global__ void __launch_bounds__(NTH, 1)
kernelA(const float* __restrict__ kin, const float* __restrict__ pe){
    extern __shared__ char smem[];
    const int tid = threadIdx.x, wid = tid >> 5;
    const int gbase = blockIdx.x * 8;

    WPipe wp;
    wp.wb[0] = smem_u32(smem + WA0);
    wp.wb[1] = smem_u32(smem + WA1);
    wp.ch = 0;
    wp.init_dst();
    wp.issue(0, 2);
    wp.issue(1, 2);

    for (int it = 0; it < 32; it++){
        int i = tid + it * NTH;
        int fq = i & 31, h = (i >> 5) & 1, n = i >> 6;
        int wi = n >> 4, lr = n & 15, r = 2 * lr + h;
        int g = gbase + wi, b_ = g / 511, j = g - b_ * 511;
        const float4 kv = *reinterpret_cast<const float4*>(
            kin + ((size_t)b_ * 8192 + 16 * j + r) * 128 + fq * 4);
        const float4 pv = *reinterpret_cast<const float4*>(pe + r * 128 + fq * 4);
        float x0 = kv.x + pv.x, x1 = kv.y + pv.y;
        float x2 = kv.z + pv.z, x3 = kv.w + pv.w;
        float h0 = bfr(x0), h1 = bfr(x1), h2 = bfr(x2), h3 = bfr(x3);
        uint2 hh, ll;
        hh.x = pack2(h0, h1);           hh.y = pack2(h2, h3);
        ll.x = pack2(x0 - h0, x1 - h1); ll.y = pack2(x2 - h2, x3 - h3);
        uint32_t off = swzA((uint32_t)n * 512u + (uint32_t)h * 256u + (uint32_t)fq * 8u);
        *reinterpret_cast<uint2*>(smem + XAH + off) = hh;
        *reinterpret_cast<uint2*>(smem + XAL + off) = ll;
    }

    run_stage<16,0,2>(smem, XAH, XAL, XBH, XBL, 0, gbase, wp, wid * 16, 0, 8);
    run_stage< 8,0,2>(smem, XBH, XBL, XAH, XAL, 0, gbase, wp,
                      (wid >> 1) * 16, (wid & 1) * 64, 8);
    run_stage< 4,3,2>(smem, XAH, XAL, 0, 0, 0, gbase, wp,
                      (wid >> 2) * 16, (wid & 3) * 32, 8);
    CPWAIT0();
}

// Kernel B: stages 3-5, 32 windows/CTA (511 CTAs).
__global__ void __launch_bounds__(NTH, 1)
kernelB(float* __restrict__ out){
    extern __shared__ char smem[];
    const int tid = threadIdx.x, wid = tid >> 5;
    const int wb = blockIdx.x * 32;

    WPipe wp;
#pragma unroll
    for (int i = 0; i < 4; i++) wp.wb[i] = smem_u32(smem + BW0 + i * 16384);
    wp.ch = 24;
    wp.init_dst();
    wp.issue(24, 4);
    wp.issue(25, 4);
    wp.issue(26, 4);

    // load stage3 input: 64 rows x 256 bf16 (hi/lo) from g_mid
    for (int i = 0; i < 16; i++){
        int e = tid + i * 256;          // 4096 uint4 total
        int half = e >> 11, rem = e & 2047;
        int row = rem >> 5, u = rem & 31;
        uint4 v = reinterpret_cast<const uint4*>(g_mid[half])[
            (size_t)(wb * 2 + row) * 32 + u];
        uint32_t off = swzA((uint32_t)row * 512u + (uint32_t)u * 16u);
        *reinterpret_cast<uint4*>(smem + (half ? BXAL : BXAH) + off) = v;
    }

    run_stage< 8,0,4>(smem, BXAH, BXAL, BXBH, BXBL, 0, wb, wp,
                      (wid >> 1) * 16, (wid & 1) * 64, 8);
    run_stage< 4,1,4>(smem, BXBH, BXBL, BX2H, BX2L, 0, wb, wp,
                      (wid >> 2) * 16, (wid & 3) * 32, 8);
    run_stage< 4,2,4>(smem, BX2H, BX2L, 0, 0, out, wb, wp,
                      (wid >> 2) * 16, (wid & 3) * 32, 4);
    CPWAIT0();
}

__global__ void prep_kernel(const float* __restrict__ wdown,
                            const float* __restrict__ wstop){
    int idx = blockIdx.x * blockDim.x + threadIdx.x;
    if (idx >= 192512) return;
    if (idx >= 180224){ g_wq[idx] = 0u; return; }
    int buf, n, i;
    const float* src;
    if (idx < 163840){
        int s = idx >> 15, rem = idx & 32767;
        int c = rem >> 12; buf = (rem >> 11) & 1;
        int w = rem & 2047; n = w >> 4; i = c * 32 + (w & 15) * 2;
        src = wdown + s * 32768 + n * 256 + i;
    } else {
        int r2 = idx - 163840;
        int c = r2 >> 12; buf = (r2 >> 11) & 1;
        int w = r2 & 2047; n = w >> 4; i = c * 32 + (w & 15) * 2;
        src = wstop + n * 128 + i;
    }
    float a = src[0], b = src[1];
    if (buf){
        a -= __bfloat162float(__float2bfloat16(a));
        b -= __bfloat162float(__float2bfloat16(b));
    }
    __nv_bfloat162 t = __floats2bfloat162_rn(a, b);
    g_wq[idx] = *reinterpret_cast<uint32_t*>(&t);
}

__global__ void zero_slot0_kernel(float* __restrict__ out){
    int i = blockIdx.x * blockDim.x + threadIdx.x;   // 4096
    out[(i >> 7) * 65536 + (i & 127)] = 0.0f;
}

extern "C" void kernel_launch(void* const* d_in, const int* in_sizes, int n_in,
                              void* d_out, int out_size){
    const float* kin   = (const float*)d_in[0];
    const float* pe    = (const float*)d_in[1];
    const float* wdown = (const float*)d_in[2];
    const float* wstop = (const float*)d_in[3];
    float* out = (float*)d_out;

    cudaFuncSetAttribute(kernelA,
                         cudaFuncAttributeMaxDynamicSharedMemorySize, SMEM_A);
    cudaFuncSetAttribute(kernelB,
                         cudaFuncAttributeMaxDynamicSharedMemorySize, SMEM_B);
    prep_kernel<<<752, 256>>>(wdown, wstop);
    zero_slot0_kernel<<<16, 256>>>(out);
    kernelA<<<2044, NTH, SMEM_A>>>(kin, pe);
    kernelB<<<511, NTH, SMEM_B>>>(out);
}